// round 1
// baseline (speedup 1.0000x reference)
#include <cuda_runtime.h>
#include <cuda_bf16.h>
#include <cstdint>

#define T_TOK 16384
#define D_DIM 1024
#define E_NUM 8
#define H_DIM 4096
#define CAP   (T_TOK / E_NUM)   // 2048

// ---------------- scratch (device globals: allocation-free) ----------------
__device__ float g_r[(size_t)T_TOK * D_DIM];          // relu(x@wr1+br1)   64MB
__device__ float g_h[(size_t)E_NUM * CAP * H_DIM];    // expert hidden    256MB
__device__ int   g_eid[T_TOK];
__device__ float g_gate[T_TOK];
__device__ int   g_idx[E_NUM * CAP];
__device__ float g_gateslot[E_NUM * CAP];

// ---------------- zero-fill output ----------------
__global__ void zero_out_kernel(float4* out, int n4) {
    int i = blockIdx.x * blockDim.x + threadIdx.x;
    if (i < n4) out[i] = make_float4(0.f, 0.f, 0.f, 0.f);
}

// ---------------- generic tiled fp32 GEMM ----------------
// C[M,N] = op(A[M,K] @ B[K,N] + bias[N])
// GATHER:  A row m is x[idx[m]] (idx==T_TOK -> zero row)
// SCATTER: output row m goes to out[idx[m]] scaled by gate[m]; idx==T_TOK skipped
template<bool GATHER, bool RELU, bool SCATTER>
__global__ void __launch_bounds__(256)
sgemm_kernel(const float* __restrict__ A, const float* __restrict__ Bmat,
             const float* __restrict__ bias, float* __restrict__ Cout,
             int M, int N, int K,
             const int* __restrict__ rowidx, const float* __restrict__ gates,
             size_t sA, size_t sB, size_t sBias, size_t sC)
{
    constexpr int BM = 128, BN = 128, BK = 16;

    const int e = blockIdx.z;
    const float* Ae   = A    + (size_t)e * sA;
    const float* Be   = Bmat + (size_t)e * sB;
    const float* be   = bias + (size_t)e * sBias;
    float*       Ce   = Cout + (size_t)e * sC;
    const int*   idxe = (GATHER || SCATTER) ? rowidx + e * CAP : nullptr;
    const float* gte  = SCATTER ? gates + e * CAP : nullptr;

    const int bm0 = blockIdx.y * BM;
    const int bn0 = blockIdx.x * BN;
    const int tid = threadIdx.x;
    const int tx = tid & 15;
    const int ty = tid >> 4;

    __shared__ float As[BK][BM];
    __shared__ float Bs[BK][BN];
    __shared__ int   sRow[BM];

    if (tid < BM) {
        sRow[tid] = (GATHER || SCATTER) ? idxe[bm0 + tid] : (bm0 + tid);
    }
    __syncthreads();

    float acc[8][8];
#pragma unroll
    for (int i = 0; i < 8; i++)
#pragma unroll
        for (int j = 0; j < 8; j++) acc[i][j] = 0.f;

    for (int k0 = 0; k0 < K; k0 += BK) {
        // load A tile (128 x 16), store transposed
#pragma unroll
        for (int l = 0; l < 2; l++) {
            int i4  = tid + l * 256;          // 0..511
            int row = i4 >> 2;                // 0..127
            int c4  = (i4 & 3) * 4;           // 0,4,8,12
            float4 v;
            if (GATHER) {
                int src = sRow[row];
                if (src >= T_TOK) v = make_float4(0.f, 0.f, 0.f, 0.f);
                else v = *(const float4*)(Ae + (size_t)src * K + k0 + c4);
            } else {
                v = *(const float4*)(Ae + (size_t)(bm0 + row) * K + k0 + c4);
            }
            As[c4 + 0][row] = v.x;
            As[c4 + 1][row] = v.y;
            As[c4 + 2][row] = v.z;
            As[c4 + 3][row] = v.w;
        }
        // load B tile (16 x 128)
#pragma unroll
        for (int l = 0; l < 2; l++) {
            int i4  = tid + l * 256;
            int row = i4 >> 5;                // 0..15
            int c4  = (i4 & 31) * 4;          // 0..124
            *(float4*)(&Bs[row][c4]) =
                *(const float4*)(Be + (size_t)(k0 + row) * N + bn0 + c4);
        }
        __syncthreads();

#pragma unroll
        for (int kk = 0; kk < BK; kk++) {
            float a[8], b[8];
            *(float4*)(a)     = *(const float4*)(&As[kk][ty * 8]);
            *(float4*)(a + 4) = *(const float4*)(&As[kk][ty * 8 + 4]);
            *(float4*)(b)     = *(const float4*)(&Bs[kk][tx * 8]);
            *(float4*)(b + 4) = *(const float4*)(&Bs[kk][tx * 8 + 4]);
#pragma unroll
            for (int i = 0; i < 8; i++)
#pragma unroll
                for (int j = 0; j < 8; j++)
                    acc[i][j] = fmaf(a[i], b[j], acc[i][j]);
        }
        __syncthreads();
    }

    float bv[8];
#pragma unroll
    for (int j = 0; j < 8; j++) bv[j] = be[bn0 + tx * 8 + j];

#pragma unroll
    for (int i = 0; i < 8; i++) {
        int lm = ty * 8 + i;
        float* dst;
        float scale = 1.f;
        if (SCATTER) {
            int token = sRow[lm];
            if (token >= T_TOK) continue;
            dst = Cout + (size_t)token * N + bn0 + tx * 8;
            scale = gte[bm0 + lm];
        } else {
            dst = Ce + (size_t)(bm0 + lm) * N + bn0 + tx * 8;
        }
        float o[8];
#pragma unroll
        for (int j = 0; j < 8; j++) {
            float v = acc[i][j] + bv[j];
            if (RELU) v = fmaxf(v, 0.f);
            if (SCATTER) v *= scale;
            o[j] = v;
        }
        *(float4*)(dst)     = *(float4*)(o);
        *(float4*)(dst + 4) = *(float4*)(o + 4);
    }
}

// ---------------- router logits + softmax-at-argmax ----------------
// one warp per token: logits = r_row @ wr2 + br2; eid = argmax (first-max);
// gate = softmax(logits)[eid] = 1 / sum(exp(l - lmax))
__global__ void router_logits_kernel(const float* __restrict__ r,
                                     const float* __restrict__ wr2,
                                     const float* __restrict__ br2,
                                     int* __restrict__ eid,
                                     float* __restrict__ gate)
{
    int warp = threadIdx.x >> 5;
    int lane = threadIdx.x & 31;
    int t = blockIdx.x * (blockDim.x >> 5) + warp;
    if (t >= T_TOK) return;

    float acc[E_NUM];
#pragma unroll
    for (int e = 0; e < E_NUM; e++) acc[e] = 0.f;

    const float* row = r + (size_t)t * D_DIM;
    for (int k = lane; k < D_DIM; k += 32) {
        float rv = row[k];
        const float* w = wr2 + (size_t)k * E_NUM;
#pragma unroll
        for (int e = 0; e < E_NUM; e++) acc[e] = fmaf(rv, w[e], acc[e]);
    }
#pragma unroll
    for (int e = 0; e < E_NUM; e++) {
#pragma unroll
        for (int off = 16; off > 0; off >>= 1)
            acc[e] += __shfl_xor_sync(0xFFFFFFFFu, acc[e], off);
    }
    if (lane == 0) {
        float l[E_NUM];
        float lmax = -1e30f;
        int   best = 0;
#pragma unroll
        for (int e = 0; e < E_NUM; e++) {
            l[e] = acc[e] + br2[e];
            if (l[e] > lmax) { lmax = l[e]; best = e; }   // first-max tie-break
        }
        float s = 0.f;
#pragma unroll
        for (int e = 0; e < E_NUM; e++) s += __expf(l[e] - lmax);
        eid[t]  = best;
        gate[t] = 1.f / s;
    }
}

// ---------------- capacity routing ----------------
__global__ void init_idx_kernel(int* idx, float* gs) {
    int i = blockIdx.x * blockDim.x + threadIdx.x;
    if (i < E_NUM * CAP) { idx[i] = T_TOK; gs[i] = 0.f; }
}

// one block per expert; token-ordered prefix count (matches reference cumsum)
__global__ void route_scan_kernel(const int* __restrict__ eid,
                                  const float* __restrict__ gate,
                                  int* __restrict__ idx,
                                  float* __restrict__ gateslot)
{
    const int e = blockIdx.x;
    const int tid = threadIdx.x;
    __shared__ int sc[256];
    int base = 0;
    for (int start = 0; start < T_TOK; start += 256) {
        int t = start + tid;
        int m = (eid[t] == e) ? 1 : 0;
        sc[tid] = m;
        __syncthreads();
#pragma unroll
        for (int off = 1; off < 256; off <<= 1) {
            int add = (tid >= off) ? sc[tid - off] : 0;
            __syncthreads();
            sc[tid] += add;
            __syncthreads();
        }
        int incl  = sc[tid];
        int total = sc[255];
        if (m) {
            int p = base + incl - 1;
            if (p < CAP) {
                idx[e * CAP + p]      = t;
                gateslot[e * CAP + p] = gate[t];
            }
        }
        base += total;
        __syncthreads();
    }
}

// ---------------- launch ----------------
extern "C" void kernel_launch(void* const* d_in, const int* in_sizes, int n_in,
                              void* d_out, int out_size)
{
    const float* x   = (const float*)d_in[0];
    const float* wr1 = (const float*)d_in[1];
    const float* br1 = (const float*)d_in[2];
    const float* wr2 = (const float*)d_in[3];
    const float* br2 = (const float*)d_in[4];
    const float* w1  = (const float*)d_in[5];
    const float* b1  = (const float*)d_in[6];
    const float* w2  = (const float*)d_in[7];
    const float* b2  = (const float*)d_in[8];
    float* out = (float*)d_out;

    float *r_ptr, *h_ptr, *gate_ptr, *gs_ptr;
    int   *eid_ptr, *idx_ptr;
    cudaGetSymbolAddress((void**)&r_ptr,    g_r);
    cudaGetSymbolAddress((void**)&h_ptr,    g_h);
    cudaGetSymbolAddress((void**)&gate_ptr, g_gate);
    cudaGetSymbolAddress((void**)&gs_ptr,   g_gateslot);
    cudaGetSymbolAddress((void**)&eid_ptr,  g_eid);
    cudaGetSymbolAddress((void**)&idx_ptr,  g_idx);

    // zero output (dropped tokens stay 0)
    {
        int n4 = ((size_t)T_TOK * D_DIM) / 4;
        zero_out_kernel<<<(n4 + 255) / 256, 256>>>((float4*)out, n4);
    }

    // 1) r = relu(x @ wr1 + br1)
    {
        dim3 grid(D_DIM / 128, T_TOK / 128, 1);
        sgemm_kernel<false, true, false><<<grid, 256>>>(
            x, wr1, br1, r_ptr, T_TOK, D_DIM, D_DIM,
            nullptr, nullptr, 0, 0, 0, 0);
    }

    // 2) logits -> eid, gate
    {
        int warps_per_block = 8;
        int blocks = T_TOK / warps_per_block;
        router_logits_kernel<<<blocks, warps_per_block * 32>>>(
            r_ptr, wr2, br2, eid_ptr, gate_ptr);
    }

    // 3) routing
    init_idx_kernel<<<(E_NUM * CAP + 255) / 256, 256>>>(idx_ptr, gs_ptr);
    route_scan_kernel<<<E_NUM, 256>>>(eid_ptr, gate_ptr, idx_ptr, gs_ptr);

    // 4) h[e] = relu(gather(x, idx[e]) @ w1[e] + b1[e])
    {
        dim3 grid(H_DIM / 128, CAP / 128, E_NUM);
        sgemm_kernel<true, true, false><<<grid, 256>>>(
            x, w1, b1, h_ptr, CAP, H_DIM, D_DIM,
            idx_ptr, nullptr,
            0, (size_t)D_DIM * H_DIM, H_DIM, (size_t)CAP * H_DIM);
    }

    // 5) out[idx] = gate * (h[e] @ w2[e] + b2[e])
    {
        dim3 grid(D_DIM / 128, CAP / 128, E_NUM);
        sgemm_kernel<false, false, true><<<grid, 256>>>(
            h_ptr, w2, b2, out, CAP, D_DIM, H_DIM,
            idx_ptr, gs_ptr,
            (size_t)CAP * H_DIM, (size_t)H_DIM * D_DIM, D_DIM, 0);
    }
}

// round 2
// speedup vs baseline: 2.2969x; 2.2969x over previous
#include <cuda_runtime.h>
#include <cuda_bf16.h>
#include <cstdint>

#define T_TOK 16384
#define D_DIM 1024
#define E_NUM 8
#define H_DIM 4096
#define CAP   (T_TOK / E_NUM)   // 2048

// ---------------- scratch (device globals: allocation-free) ----------------
__device__ float g_r[(size_t)T_TOK * D_DIM];          // relu(x@wr1+br1)   64MB
__device__ float g_h[(size_t)E_NUM * CAP * H_DIM];    // expert hidden    256MB
__device__ int   g_eid[T_TOK];
__device__ float g_gate[T_TOK];
__device__ int   g_idx[E_NUM * CAP];
__device__ float g_gateslot[E_NUM * CAP];

// ---------------- zero-fill output ----------------
__global__ void zero_out_kernel(float4* out, int n4) {
    int i = blockIdx.x * blockDim.x + threadIdx.x;
    if (i < n4) out[i] = make_float4(0.f, 0.f, 0.f, 0.f);
}

// ---------------- fp32 -> tf32 bits ----------------
__device__ __forceinline__ uint32_t f2tf32(float x) {
    uint32_t r;
    asm("cvt.rna.tf32.f32 %0, %1;" : "=r"(r) : "f"(x));
    return r;
}

// ---------------- m16n8k8 tf32 mma ----------------
__device__ __forceinline__ void mma_tf32(float* d,
                                         const uint32_t* a, const uint32_t* b) {
    asm volatile(
        "mma.sync.aligned.m16n8k8.row.col.f32.tf32.tf32.f32 "
        "{%0,%1,%2,%3}, {%4,%5,%6,%7}, {%8,%9}, {%0,%1,%2,%3};"
        : "+f"(d[0]), "+f"(d[1]), "+f"(d[2]), "+f"(d[3])
        : "r"(a[0]), "r"(a[1]), "r"(a[2]), "r"(a[3]),
          "r"(b[0]), "r"(b[1]));
}

// ---------------- TF32 tensor-core GEMM ----------------
// C[M,N] = op(A[M,K] @ B[K,N] + bias[N]), fp32 in/out, tf32 compute.
// GATHER:  A row m is A[idx[m]] (idx==T_TOK -> zero row)
// SCATTER: output row m goes to Cout[idx[m]]*gate[m]; idx==T_TOK skipped
template<bool GATHER, bool RELU, bool SCATTER>
__global__ void __launch_bounds__(256)
tf32gemm_kernel(const float* __restrict__ A, const float* __restrict__ Bmat,
                const float* __restrict__ bias, float* __restrict__ Cout,
                int M, int N, int K,
                const int* __restrict__ rowidx, const float* __restrict__ gates,
                size_t sA, size_t sB, size_t sBias, size_t sC)
{
    constexpr int BM = 128, BN = 128, BK = 32;

    const int e = blockIdx.z;
    const float* Ae   = A    + (size_t)e * sA;
    const float* Be   = Bmat + (size_t)e * sB;
    const float* be   = bias + (size_t)e * sBias;
    float*       Ce   = Cout + (size_t)e * sC;
    const int*   idxe = (GATHER || SCATTER) ? rowidx + e * CAP : nullptr;
    const float* gte  = SCATTER ? gates + e * CAP : nullptr;

    const int bm0 = blockIdx.y * BM;
    const int bn0 = blockIdx.x * BN;
    const int tid = threadIdx.x;
    const int warp = tid >> 5;
    const int lane = tid & 31;
    const int wr = warp >> 2;      // 0..1  (64-row slabs)
    const int wc = warp & 3;       // 0..3  (32-col slabs)
    const int lr = lane >> 2;      // 0..7
    const int lc = lane & 3;       // 0..3

    __shared__ uint32_t As[BM][BK + 4];    // bank=(4m+k)%32 -> conflict-free
    __shared__ uint32_t Bs[BK][BN + 8];    // bank=(8k+n)%32 -> conflict-free
    __shared__ int      sRow[BM];

    if (tid < BM) {
        sRow[tid] = (GATHER || SCATTER) ? idxe[bm0 + tid] : (bm0 + tid);
    }
    __syncthreads();

    float acc[4][4][4];
#pragma unroll
    for (int mt = 0; mt < 4; mt++)
#pragma unroll
        for (int nt = 0; nt < 4; nt++)
#pragma unroll
            for (int i = 0; i < 4; i++) acc[mt][nt][i] = 0.f;

    for (int k0 = 0; k0 < K; k0 += BK) {
        // ---- A tile: 128 x 32 fp32 -> tf32 smem ----
#pragma unroll
        for (int l = 0; l < 4; l++) {
            int i4  = tid + l * 256;            // 0..1023
            int row = i4 >> 3;                  // 0..127
            int c4  = (i4 & 7) * 4;             // 0,4,...,28
            float4 v;
            if (GATHER) {
                int src = sRow[row];
                if (src >= T_TOK) v = make_float4(0.f, 0.f, 0.f, 0.f);
                else v = *(const float4*)(Ae + (size_t)src * K + k0 + c4);
            } else {
                v = *(const float4*)(Ae + (size_t)(bm0 + row) * K + k0 + c4);
            }
            uint4 t;
            t.x = f2tf32(v.x); t.y = f2tf32(v.y);
            t.z = f2tf32(v.z); t.w = f2tf32(v.w);
            *(uint4*)&As[row][c4] = t;
        }
        // ---- B tile: 32 x 128 fp32 -> tf32 smem ----
#pragma unroll
        for (int l = 0; l < 4; l++) {
            int i4  = tid + l * 256;
            int row = i4 >> 5;                  // 0..31
            int c4  = (i4 & 31) * 4;            // 0..124
            float4 v = *(const float4*)(Be + (size_t)(k0 + row) * N + bn0 + c4);
            uint4 t;
            t.x = f2tf32(v.x); t.y = f2tf32(v.y);
            t.z = f2tf32(v.z); t.w = f2tf32(v.w);
            *(uint4*)&Bs[row][c4] = t;
        }
        __syncthreads();

#pragma unroll
        for (int kk = 0; kk < BK; kk += 8) {
            uint32_t a[4][4], b[4][2];
#pragma unroll
            for (int mt = 0; mt < 4; mt++) {
                int m0 = wr * 64 + mt * 16;
                a[mt][0] = As[m0 + lr    ][kk + lc    ];
                a[mt][1] = As[m0 + lr + 8][kk + lc    ];
                a[mt][2] = As[m0 + lr    ][kk + lc + 4];
                a[mt][3] = As[m0 + lr + 8][kk + lc + 4];
            }
#pragma unroll
            for (int nt = 0; nt < 4; nt++) {
                int n0 = wc * 32 + nt * 8;
                b[nt][0] = Bs[kk + lc    ][n0 + lr];
                b[nt][1] = Bs[kk + lc + 4][n0 + lr];
            }
#pragma unroll
            for (int mt = 0; mt < 4; mt++)
#pragma unroll
                for (int nt = 0; nt < 4; nt++)
                    mma_tf32(acc[mt][nt], a[mt], b[nt]);
        }
        __syncthreads();
    }

    // ---- epilogue ----
#pragma unroll
    for (int nt = 0; nt < 4; nt++) {
        int cb = wc * 32 + nt * 8 + 2 * lc;
        float bv0 = be[bn0 + cb];
        float bv1 = be[bn0 + cb + 1];
#pragma unroll
        for (int mt = 0; mt < 4; mt++) {
#pragma unroll
            for (int h = 0; h < 2; h++) {
                int lm = wr * 64 + mt * 16 + lr + h * 8;
                float v0 = acc[mt][nt][h * 2 + 0] + bv0;
                float v1 = acc[mt][nt][h * 2 + 1] + bv1;
                if (RELU) { v0 = fmaxf(v0, 0.f); v1 = fmaxf(v1, 0.f); }
                float* dst;
                if (SCATTER) {
                    int token = sRow[lm];
                    if (token >= T_TOK) continue;
                    float g = gte[bm0 + lm];
                    v0 *= g; v1 *= g;
                    dst = Cout + (size_t)token * N + bn0 + cb;
                } else {
                    dst = Ce + (size_t)(bm0 + lm) * N + bn0 + cb;
                }
                *(float2*)dst = make_float2(v0, v1);
            }
        }
    }
}

// ---------------- fp32 SIMT GEMM (router only: exactness matters) ----------------
__global__ void __launch_bounds__(256)
sgemm_router_kernel(const float* __restrict__ A, const float* __restrict__ Bmat,
                    const float* __restrict__ bias, float* __restrict__ Cout,
                    int N, int K)
{
    constexpr int BM = 128, BN = 128, BK = 16;
    const int bm0 = blockIdx.y * BM;
    const int bn0 = blockIdx.x * BN;
    const int tid = threadIdx.x;
    const int tx = tid & 15;
    const int ty = tid >> 4;

    __shared__ float As[BK][BM];
    __shared__ float Bs[BK][BN];

    float acc[8][8];
#pragma unroll
    for (int i = 0; i < 8; i++)
#pragma unroll
        for (int j = 0; j < 8; j++) acc[i][j] = 0.f;

    for (int k0 = 0; k0 < K; k0 += BK) {
#pragma unroll
        for (int l = 0; l < 2; l++) {
            int i4  = tid + l * 256;
            int row = i4 >> 2;
            int c4  = (i4 & 3) * 4;
            float4 v = *(const float4*)(A + (size_t)(bm0 + row) * K + k0 + c4);
            As[c4 + 0][row] = v.x;
            As[c4 + 1][row] = v.y;
            As[c4 + 2][row] = v.z;
            As[c4 + 3][row] = v.w;
        }
#pragma unroll
        for (int l = 0; l < 2; l++) {
            int i4  = tid + l * 256;
            int row = i4 >> 5;
            int c4  = (i4 & 31) * 4;
            *(float4*)(&Bs[row][c4]) =
                *(const float4*)(Bmat + (size_t)(k0 + row) * N + bn0 + c4);
        }
        __syncthreads();

#pragma unroll
        for (int kk = 0; kk < BK; kk++) {
            float a[8], b[8];
            *(float4*)(a)     = *(const float4*)(&As[kk][ty * 8]);
            *(float4*)(a + 4) = *(const float4*)(&As[kk][ty * 8 + 4]);
            *(float4*)(b)     = *(const float4*)(&Bs[kk][tx * 8]);
            *(float4*)(b + 4) = *(const float4*)(&Bs[kk][tx * 8 + 4]);
#pragma unroll
            for (int i = 0; i < 8; i++)
#pragma unroll
                for (int j = 0; j < 8; j++)
                    acc[i][j] = fmaf(a[i], b[j], acc[i][j]);
        }
        __syncthreads();
    }

    float bv[8];
#pragma unroll
    for (int j = 0; j < 8; j++) bv[j] = bias[bn0 + tx * 8 + j];

#pragma unroll
    for (int i = 0; i < 8; i++) {
        float* dst = Cout + (size_t)(bm0 + ty * 8 + i) * N + bn0 + tx * 8;
        float o[8];
#pragma unroll
        for (int j = 0; j < 8; j++) o[j] = fmaxf(acc[i][j] + bv[j], 0.f);
        *(float4*)(dst)     = *(float4*)(o);
        *(float4*)(dst + 4) = *(float4*)(o + 4);
    }
}

// ---------------- router logits + softmax-at-argmax ----------------
__global__ void router_logits_kernel(const float* __restrict__ r,
                                     const float* __restrict__ wr2,
                                     const float* __restrict__ br2,
                                     int* __restrict__ eid,
                                     float* __restrict__ gate)
{
    int warp = threadIdx.x >> 5;
    int lane = threadIdx.x & 31;
    int t = blockIdx.x * (blockDim.x >> 5) + warp;
    if (t >= T_TOK) return;

    float acc[E_NUM];
#pragma unroll
    for (int e = 0; e < E_NUM; e++) acc[e] = 0.f;

    const float* row = r + (size_t)t * D_DIM;
    for (int k = lane; k < D_DIM; k += 32) {
        float rv = row[k];
        const float* w = wr2 + (size_t)k * E_NUM;
#pragma unroll
        for (int e = 0; e < E_NUM; e++) acc[e] = fmaf(rv, w[e], acc[e]);
    }
#pragma unroll
    for (int e = 0; e < E_NUM; e++) {
#pragma unroll
        for (int off = 16; off > 0; off >>= 1)
            acc[e] += __shfl_xor_sync(0xFFFFFFFFu, acc[e], off);
    }
    if (lane == 0) {
        float l[E_NUM];
        float lmax = -1e30f;
        int   best = 0;
#pragma unroll
        for (int e = 0; e < E_NUM; e++) {
            l[e] = acc[e] + br2[e];
            if (l[e] > lmax) { lmax = l[e]; best = e; }   // first-max tie-break
        }
        float s = 0.f;
#pragma unroll
        for (int e = 0; e < E_NUM; e++) s += __expf(l[e] - lmax);
        eid[t]  = best;
        gate[t] = 1.f / s;
    }
}

// ---------------- capacity routing ----------------
__global__ void init_idx_kernel(int* idx, float* gs) {
    int i = blockIdx.x * blockDim.x + threadIdx.x;
    if (i < E_NUM * CAP) { idx[i] = T_TOK; gs[i] = 0.f; }
}

__global__ void route_scan_kernel(const int* __restrict__ eid,
                                  const float* __restrict__ gate,
                                  int* __restrict__ idx,
                                  float* __restrict__ gateslot)
{
    const int e = blockIdx.x;
    const int tid = threadIdx.x;
    __shared__ int sc[256];
    int base = 0;
    for (int start = 0; start < T_TOK; start += 256) {
        int t = start + tid;
        int m = (eid[t] == e) ? 1 : 0;
        sc[tid] = m;
        __syncthreads();
#pragma unroll
        for (int off = 1; off < 256; off <<= 1) {
            int add = (tid >= off) ? sc[tid - off] : 0;
            __syncthreads();
            sc[tid] += add;
            __syncthreads();
        }
        int incl  = sc[tid];
        int total = sc[255];
        if (m) {
            int p = base + incl - 1;
            if (p < CAP) {
                idx[e * CAP + p]      = t;
                gateslot[e * CAP + p] = gate[t];
            }
        }
        base += total;
        __syncthreads();
    }
}

// ---------------- launch ----------------
extern "C" void kernel_launch(void* const* d_in, const int* in_sizes, int n_in,
                              void* d_out, int out_size)
{
    const float* x   = (const float*)d_in[0];
    const float* wr1 = (const float*)d_in[1];
    const float* br1 = (const float*)d_in[2];
    const float* wr2 = (const float*)d_in[3];
    const float* br2 = (const float*)d_in[4];
    const float* w1  = (const float*)d_in[5];
    const float* b1  = (const float*)d_in[6];
    const float* w2  = (const float*)d_in[7];
    const float* b2  = (const float*)d_in[8];
    float* out = (float*)d_out;

    float *r_ptr, *h_ptr, *gate_ptr, *gs_ptr;
    int   *eid_ptr, *idx_ptr;
    cudaGetSymbolAddress((void**)&r_ptr,    g_r);
    cudaGetSymbolAddress((void**)&h_ptr,    g_h);
    cudaGetSymbolAddress((void**)&gate_ptr, g_gate);
    cudaGetSymbolAddress((void**)&gs_ptr,   g_gateslot);
    cudaGetSymbolAddress((void**)&eid_ptr,  g_eid);
    cudaGetSymbolAddress((void**)&idx_ptr,  g_idx);

    // zero output (dropped tokens stay 0)
    {
        int n4 = ((size_t)T_TOK * D_DIM) / 4;
        zero_out_kernel<<<(n4 + 255) / 256, 256>>>((float4*)out, n4);
    }

    // 1) r = relu(x @ wr1 + br1)   -- exact fp32 (routing depends on it)
    {
        dim3 grid(D_DIM / 128, T_TOK / 128, 1);
        sgemm_router_kernel<<<grid, 256>>>(x, wr1, br1, r_ptr, D_DIM, D_DIM);
    }

    // 2) logits -> eid, gate  (fp32)
    {
        int warps_per_block = 8;
        int blocks = T_TOK / warps_per_block;
        router_logits_kernel<<<blocks, warps_per_block * 32>>>(
            r_ptr, wr2, br2, eid_ptr, gate_ptr);
    }

    // 3) routing
    init_idx_kernel<<<(E_NUM * CAP + 255) / 256, 256>>>(idx_ptr, gs_ptr);
    route_scan_kernel<<<E_NUM, 256>>>(eid_ptr, gate_ptr, idx_ptr, gs_ptr);

    // 4) h[e] = relu(gather(x, idx[e]) @ w1[e] + b1[e])   -- tf32 tensor cores
    {
        dim3 grid(H_DIM / 128, CAP / 128, E_NUM);
        tf32gemm_kernel<true, true, false><<<grid, 256>>>(
            x, w1, b1, h_ptr, CAP, H_DIM, D_DIM,
            idx_ptr, nullptr,
            0, (size_t)D_DIM * H_DIM, H_DIM, (size_t)CAP * H_DIM);
    }

    // 5) out[idx] = gate * (h[e] @ w2[e] + b2[e])   -- tf32 tensor cores
    {
        dim3 grid(D_DIM / 128, CAP / 128, E_NUM);
        tf32gemm_kernel<false, false, true><<<grid, 256>>>(
            h_ptr, w2, b2, out, CAP, D_DIM, H_DIM,
            idx_ptr, gs_ptr,
            (size_t)CAP * H_DIM, (size_t)H_DIM * D_DIM, D_DIM, 0);
    }
}